// round 1
// baseline (speedup 1.0000x reference)
#include <cuda_runtime.h>
#include <math.h>

#define S_LEN   2048
#define HID_DIM 3584
#define NH      16
#define NKV     8
#define HD      256
#define QKV_N   ((NH + 2 * NKV) * HD)   // 8192
#define ATTN_N  (NH * HD)               // 4096
#define WIN     1024
#define SOFTCAP 50.0f
#define SCALING 0.0625f                 // 256^-0.5

// Scratch (allocation-free rule: __device__ globals)
__device__ float g_qkv[S_LEN * QKV_N];   // 64 MB
__device__ float g_attn[S_LEN * ATTN_N]; // 32 MB

// ---------------------------------------------------------------------------
// Classic 128x128x8 SGEMM, 256 threads, 8x8 per thread. All dims divide tiles.
// C[M,N] = A[M,K] @ B[K,N], row-major.
// ---------------------------------------------------------------------------
#define BM 128
#define BN 128
#define BK 8
#define TM 8
#define TN 8

__global__ void __launch_bounds__(256)
sgemm_kernel(const float* __restrict__ A, const float* __restrict__ B,
             float* __restrict__ C, int M, int N, int K)
{
    __shared__ float As[BK][BM];
    __shared__ float Bs[BK][BN];

    const int tid  = threadIdx.x;
    const int cRow = blockIdx.y * BM;
    const int cCol = blockIdx.x * BN;

    const int tx = tid & 15;   // N direction, 16 threads
    const int ty = tid >> 4;   // M direction, 16 threads

    float acc[TM][TN] = {};
    float regM[TM], regN[TN];

    // A tile loaders: BM x BK = 1024 floats -> 256 float4
    const int aRow = tid >> 1;          // 0..127
    const int aCol = (tid & 1) * 4;     // 0 or 4
    // B tile loaders: BK x BN = 1024 floats
    const int bRow = tid >> 5;          // 0..7
    const int bCol = (tid & 31) * 4;    // 0..124

    const float* Aptr = A + (size_t)cRow * K;
    const float* Bptr = B + cCol;

    for (int k0 = 0; k0 < K; k0 += BK) {
        float4 a4 = *reinterpret_cast<const float4*>(Aptr + (size_t)aRow * K + k0 + aCol);
        As[aCol + 0][aRow] = a4.x;
        As[aCol + 1][aRow] = a4.y;
        As[aCol + 2][aRow] = a4.z;
        As[aCol + 3][aRow] = a4.w;
        float4 b4 = *reinterpret_cast<const float4*>(Bptr + (size_t)(k0 + bRow) * N + bCol);
        *reinterpret_cast<float4*>(&Bs[bRow][bCol]) = b4;
        __syncthreads();

        #pragma unroll
        for (int kk = 0; kk < BK; kk++) {
            #pragma unroll
            for (int i = 0; i < TM; i++) regM[i] = As[kk][ty * TM + i];
            #pragma unroll
            for (int j = 0; j < TN; j++) regN[j] = Bs[kk][tx * TN + j];
            #pragma unroll
            for (int i = 0; i < TM; i++)
                #pragma unroll
                for (int j = 0; j < TN; j++)
                    acc[i][j] += regM[i] * regN[j];
        }
        __syncthreads();
    }

    #pragma unroll
    for (int i = 0; i < TM; i++) {
        const size_t row = cRow + ty * TM + i;
        #pragma unroll
        for (int j = 0; j < TN; j += 4) {
            float4 v = make_float4(acc[i][j], acc[i][j + 1], acc[i][j + 2], acc[i][j + 3]);
            *reinterpret_cast<float4*>(C + row * N + cCol + tx * TN + j) = v;
        }
    }
}

// ---------------------------------------------------------------------------
// RoPE in-place on Q (heads 0..15) and K (heads 16..23) slices of g_qkv.
// freqs_cos/sin: [S, HD/2]
// ---------------------------------------------------------------------------
__global__ void rope_kernel(const float* __restrict__ fcos, const float* __restrict__ fsin)
{
    const int s = blockIdx.x;
    const float* crow = fcos + (size_t)s * (HD / 2);
    const float* srow = fsin + (size_t)s * (HD / 2);
    float* row = g_qkv + (size_t)s * QKV_N;

    for (int p = threadIdx.x; p < (NH + NKV) * (HD / 2); p += blockDim.x) {
        const int h = p / (HD / 2);
        const int d = p % (HD / 2);
        const float c  = crow[d];
        const float sn = srow[d];
        const float x1 = row[h * HD + d];
        const float x2 = row[h * HD + d + HD / 2];
        row[h * HD + d]          = x1 * c - x2 * sn;
        row[h * HD + d + HD / 2] = x1 * sn + x2 * c;
    }
}

// ---------------------------------------------------------------------------
// Flash attention with sliding window + softcap.
// Softcap bounds scores to [-50,50] => fixed softmax max of 50: p = exp(t-50),
// no online rescaling. One CTA per (64-query block, head).
// ---------------------------------------------------------------------------
#define BQ   64
#define BKV  32
#define QPAD (HD + 4)   // 260 floats/row, keeps float4 alignment, breaks bank conflicts

__global__ void __launch_bounds__(256, 1) attn_kernel()
{
    extern __shared__ float sm[];
    float* sQ   = sm;                      // BQ  * QPAD
    float* sK   = sQ + BQ * QPAD;          // BKV * QPAD
    float* sV   = sK + BKV * QPAD;         // BKV * QPAD
    float* sP   = sV + BKV * QPAD;         // BQ  * 33
    float* sSum = sP + BQ * 33;            // BQ

    const int tid = threadIdx.x;
    const int tx  = tid & 15;   // 16 -> k cols (2 each) / d cols (16 each)
    const int ty  = tid >> 4;   // 16 -> q rows (4 each)
    const int q0  = blockIdx.x * BQ;
    const int h   = blockIdx.y;
    const int kvh = h >> 1;     // GQA group = 2

    // Load Q tile (pre-scaled)
    for (int i = tid; i < BQ * HD; i += 256) {
        const int r = i >> 8;
        const int d = i & 255;
        sQ[r * QPAD + d] = g_qkv[(size_t)(q0 + r) * QKV_N + h * HD + d] * SCALING;
    }
    if (tid < BQ) sSum[tid] = 0.f;

    float acc[4][16] = {};
    float psum[4]    = {0.f, 0.f, 0.f, 0.f};

    const int klo      = max(0, q0 - (WIN - 1));
    const int kb_start = (klo / BKV) * BKV;
    const int kb_end   = q0 + BQ;

    __syncthreads();

    for (int kb = kb_start; kb < kb_end; kb += BKV) {
        // Stage K,V tiles: 32 x 256 floats each
        for (int i = tid; i < BKV * (HD / 4); i += 256) {
            const int r  = i / (HD / 4);
            const int d4 = i % (HD / 4);
            const size_t base = (size_t)(kb + r) * QKV_N;
            float4 k4 = *reinterpret_cast<const float4*>(&g_qkv[base + (NH + kvh) * HD + d4 * 4]);
            *reinterpret_cast<float4*>(&sK[r * QPAD + d4 * 4]) = k4;
            float4 v4 = *reinterpret_cast<const float4*>(&g_qkv[base + (NH + NKV + kvh) * HD + d4 * 4]);
            *reinterpret_cast<float4*>(&sV[r * QPAD + d4 * 4]) = v4;
        }
        __syncthreads();

        // Scores: each thread 4 q x 2 k, dot over 256 dims (float4 strides)
        float sacc[4][2] = {};
        #pragma unroll 8
        for (int d4 = 0; d4 < HD / 4; d4++) {
            float4 qv[4];
            #pragma unroll
            for (int i = 0; i < 4; i++)
                qv[i] = *reinterpret_cast<const float4*>(&sQ[(ty * 4 + i) * QPAD + d4 * 4]);
            float4 kv[2];
            #pragma unroll
            for (int j = 0; j < 2; j++)
                kv[j] = *reinterpret_cast<const float4*>(&sK[(tx * 2 + j) * QPAD + d4 * 4]);
            #pragma unroll
            for (int i = 0; i < 4; i++)
                #pragma unroll
                for (int j = 0; j < 2; j++)
                    sacc[i][j] += qv[i].x * kv[j].x + qv[i].y * kv[j].y
                                + qv[i].z * kv[j].z + qv[i].w * kv[j].w;
        }

        // Softcap + window/causal mask + exp(t - 50)
        #pragma unroll
        for (int i = 0; i < 4; i++) {
            const int q = q0 + ty * 4 + i;
            #pragma unroll
            for (int j = 0; j < 2; j++) {
                const int k = kb + tx * 2 + j;
                const float t = tanhf(sacc[i][j] * (1.0f / SOFTCAP)) * SOFTCAP;
                float p = __expf(t - SOFTCAP);
                const bool valid = (k <= q) && (q - k < WIN);
                p = valid ? p : 0.f;
                sP[(ty * 4 + i) * 33 + tx * 2 + j] = p;
                psum[i] += p;
            }
        }
        __syncthreads();

        // PV: out[q][d] += P[q][k] * V[k][d]; each thread 4 q x 16 d
        #pragma unroll
        for (int kk = 0; kk < BKV; kk++) {
            float pv[4];
            #pragma unroll
            for (int i = 0; i < 4; i++) pv[i] = sP[(ty * 4 + i) * 33 + kk];
            float4 vv[4];
            #pragma unroll
            for (int j4 = 0; j4 < 4; j4++)
                vv[j4] = *reinterpret_cast<const float4*>(&sV[kk * QPAD + tx * 16 + j4 * 4]);
            #pragma unroll
            for (int i = 0; i < 4; i++) {
                #pragma unroll
                for (int j4 = 0; j4 < 4; j4++) {
                    acc[i][j4 * 4 + 0] += pv[i] * vv[j4].x;
                    acc[i][j4 * 4 + 1] += pv[i] * vv[j4].y;
                    acc[i][j4 * 4 + 2] += pv[i] * vv[j4].z;
                    acc[i][j4 * 4 + 3] += pv[i] * vv[j4].w;
                }
            }
        }
        __syncthreads();
    }

    // Row-sum reduction across tx
    #pragma unroll
    for (int i = 0; i < 4; i++) atomicAdd(&sSum[ty * 4 + i], psum[i]);
    __syncthreads();

    // Normalize and write: g_attn[q][h*HD + d]
    #pragma unroll
    for (int i = 0; i < 4; i++) {
        const size_t q  = q0 + ty * 4 + i;
        const float inv = 1.0f / sSum[ty * 4 + i];
        #pragma unroll
        for (int j4 = 0; j4 < 4; j4++) {
            float4 o;
            o.x = acc[i][j4 * 4 + 0] * inv;
            o.y = acc[i][j4 * 4 + 1] * inv;
            o.z = acc[i][j4 * 4 + 2] * inv;
            o.w = acc[i][j4 * 4 + 3] * inv;
            *reinterpret_cast<float4*>(&g_attn[q * ATTN_N + h * HD + tx * 16 + j4 * 4]) = o;
        }
    }
}

// ---------------------------------------------------------------------------
extern "C" void kernel_launch(void* const* d_in, const int* in_sizes, int n_in,
                              void* d_out, int out_size)
{
    const float* hidden = (const float*)d_in[0];
    const float* Wqkv   = (const float*)d_in[1];
    const float* Wo     = (const float*)d_in[2];
    const float* fcos   = (const float*)d_in[3];
    const float* fsin   = (const float*)d_in[4];
    // d_in[5] (mask) unused: band+causal computed analytically
    float* out = (float*)d_out;

    float* qkv_ptr  = nullptr;
    float* attn_ptr = nullptr;
    cudaGetSymbolAddress((void**)&qkv_ptr, g_qkv);
    cudaGetSymbolAddress((void**)&attn_ptr, g_attn);

    // 1) QKV projection: [2048,3584] @ [3584,8192]
    sgemm_kernel<<<dim3(QKV_N / BN, S_LEN / BM), 256>>>(hidden, Wqkv, qkv_ptr,
                                                        S_LEN, QKV_N, HID_DIM);
    // 2) RoPE in-place on Q,K
    rope_kernel<<<S_LEN, 256>>>(fcos, fsin);

    // 3) Windowed softcapped attention
    const int smem_bytes = (BQ * QPAD + 2 * BKV * QPAD + BQ * 33 + BQ) * (int)sizeof(float);
    cudaFuncSetAttribute(attn_kernel, cudaFuncAttributeMaxDynamicSharedMemorySize, smem_bytes);
    attn_kernel<<<dim3(S_LEN / BQ, NH), 256, smem_bytes>>>();

    // 4) Output projection: [2048,4096] @ [4096,3584]
    sgemm_kernel<<<dim3(HID_DIM / BN, S_LEN / BM), 256>>>(attn_ptr, Wo, out,
                                                          S_LEN, HID_DIM, ATTN_N);
}

// round 3
// speedup vs baseline: 2.0185x; 2.0185x over previous
#include <cuda_runtime.h>
#include <cuda_bf16.h>
#include <math.h>
#include <stdint.h>

#define S_LEN   2048
#define HID_DIM 3584
#define NH      16
#define NKV     8
#define HD      256
#define QKV_N   ((NH + 2 * NKV) * HD)   // 8192
#define ATTN_N  (NH * HD)               // 4096
#define WIN     1024
#define SOFTCAP 50.0f
#define SCALING 0.0625f

// ---------------- scratch (__device__ globals; no allocs allowed) ----------
__device__ __align__(256) float g_qkv[S_LEN * QKV_N];    // 64 MB
__device__ __align__(256) float g_attn[S_LEN * ATTN_N];  // 32 MB
__device__ __align__(256) __nv_bfloat16 g_Ah[S_LEN * 4096];
__device__ __align__(256) __nv_bfloat16 g_Al[S_LEN * 4096];
__device__ __align__(256) __nv_bfloat16 g_Bh[8192 * 3584];
__device__ __align__(256) __nv_bfloat16 g_Bl[8192 * 3584];

// ---------------- PTX helpers ----------------------------------------------
__device__ __forceinline__ uint32_t smem_u32(const void* p) {
    uint32_t a;
    asm("{ .reg .u64 t; cvta.to.shared.u64 t, %1; cvt.u32.u64 %0, t; }" : "=r"(a) : "l"(p));
    return a;
}
#define CP_ASYNC16(dst, src) \
    asm volatile("cp.async.cg.shared.global [%0], [%1], 16;" :: "r"(dst), "l"(src) : "memory")
#define CP_COMMIT() asm volatile("cp.async.commit_group;" ::: "memory")
#define CP_WAIT1()  asm volatile("cp.async.wait_group 1;" ::: "memory")

#define LDSM_X4(r0, r1, r2, r3, addr) \
    asm volatile("ldmatrix.sync.aligned.m8n8.x4.shared.b16 {%0,%1,%2,%3}, [%4];" \
        : "=r"(r0), "=r"(r1), "=r"(r2), "=r"(r3) : "r"(addr))
#define LDSM_X4T(r0, r1, r2, r3, addr) \
    asm volatile("ldmatrix.sync.aligned.m8n8.x4.trans.shared.b16 {%0,%1,%2,%3}, [%4];" \
        : "=r"(r0), "=r"(r1), "=r"(r2), "=r"(r3) : "r"(addr))

#define MMA_BF16(d, a, b0, b1) \
    asm volatile("mma.sync.aligned.m16n8k16.row.col.f32.bf16.bf16.f32 " \
        "{%0,%1,%2,%3}, {%4,%5,%6,%7}, {%8,%9}, {%0,%1,%2,%3};" \
        : "+f"((d)[0]), "+f"((d)[1]), "+f"((d)[2]), "+f"((d)[3]) \
        : "r"((a)[0]), "r"((a)[1]), "r"((a)[2]), "r"((a)[3]), "r"(b0), "r"(b1))

__device__ __forceinline__ void split_bf16(float x, __nv_bfloat16& h, __nv_bfloat16& l) {
    h = __float2bfloat16_rn(x);
    l = __float2bfloat16_rn(x - __bfloat162float(h));
}

// ---------------------------------------------------------------------------
// conv_split: fp32 row-major -> hi/lo bf16, same layout. 4 elems/thread.
// ---------------------------------------------------------------------------
__global__ void conv_split(const float4* __restrict__ X, __nv_bfloat162* __restrict__ H,
                           __nv_bfloat162* __restrict__ L)
{
    const size_t i = (size_t)blockIdx.x * blockDim.x + threadIdx.x;
    float4 v = X[i];
    __nv_bfloat16 h0, l0, h1, l1, h2, l2, h3, l3;
    split_bf16(v.x, h0, l0); split_bf16(v.y, h1, l1);
    split_bf16(v.z, h2, l2); split_bf16(v.w, h3, l3);
    __nv_bfloat162 a, b, c, d;
    a.x = h0; a.y = h1;  b.x = h2; b.y = h3;
    c.x = l0; c.y = l1;  d.x = l2; d.y = l3;
    H[2 * i] = a; H[2 * i + 1] = b;
    L[2 * i] = c; L[2 * i + 1] = d;
}

// ---------------------------------------------------------------------------
// HMMA split-bf16 GEMM: C[M,N] fp32 = A @ B.
// CTA 128x128, 8 warps (32x64 each), BK=32, cp.async double buffer.
// ---------------------------------------------------------------------------
#define BM   128
#define BN   128
#define BK   32
#define LDA  40     // 32 + 8 pad (bf16 units)
#define LDB  136    // 128 + 8 pad
#define TILE_A_B (128 * LDA * 2)            // bytes per A tile (10240)
#define TILE_B_B (32 * LDB * 2)             // bytes per B tile (8704)
#define OFF_AH   0
#define OFF_AL   (TILE_A_B)
#define OFF_BH   (2 * TILE_A_B)
#define OFF_BL   (2 * TILE_A_B + TILE_B_B)
#define STAGE_B  (2 * TILE_A_B + 2 * TILE_B_B)   // 37888
#define NSTG 2

__global__ void __launch_bounds__(256, 1)
gemm_mma(const __nv_bfloat16* __restrict__ Ah, const __nv_bfloat16* __restrict__ Al,
         const __nv_bfloat16* __restrict__ Bh, const __nv_bfloat16* __restrict__ Bl,
         float* __restrict__ C, int N, int K)
{
    extern __shared__ char smbuf[];
    const uint32_t sb = smem_u32(smbuf);

    const int tid  = threadIdx.x;
    const int lane = tid & 31;
    const int wid  = tid >> 5;
    const int wm   = (wid & 3) * 32;     // warp m offset in tile
    const int wn   = (wid >> 2) * 64;    // warp n offset in tile
    const int nb   = blockIdx.x, mbk = blockIdx.y;
    const int m0   = mbk * BM, n0 = nb * BN;
    const int KT   = K / BK;

    // loader mapping
    const int ar = tid >> 1, ac = (tid & 1) * 16;        // A: 128 rows, 2 thr/row
    const int br = tid >> 3, bc = (tid & 7) * 16;        // B: 32 rows, 8 thr/row

    const __nv_bfloat16* gAh = Ah + (size_t)(m0 + ar) * K + ac;
    const __nv_bfloat16* gAl = Al + (size_t)(m0 + ar) * K + ac;
    const __nv_bfloat16* gBh = Bh + (size_t)br * N + n0 + bc;
    const __nv_bfloat16* gBl = Bl + (size_t)br * N + n0 + bc;

    auto load_stage = [&](int s, int c) {
        const uint32_t st = sb + s * STAGE_B;
        const size_t ka = (size_t)c * BK;
        const uint32_t sa = st + (ar * LDA + ac) * 2;
        CP_ASYNC16(sa + OFF_AH,      gAh + ka);
        CP_ASYNC16(sa + OFF_AH + 16, gAh + ka + 8);
        CP_ASYNC16(sa + OFF_AL,      gAl + ka);
        CP_ASYNC16(sa + OFF_AL + 16, gAl + ka + 8);
        const uint32_t sbm = st + (br * LDB + bc) * 2;
        const size_t kb = (size_t)c * BK * N;
        CP_ASYNC16(sbm + OFF_BH,      gBh + kb);
        CP_ASYNC16(sbm + OFF_BH + 16, gBh + kb + 8);
        CP_ASYNC16(sbm + OFF_BL,      gBl + kb);
        CP_ASYNC16(sbm + OFF_BL + 16, gBl + kb + 8);
    };

    load_stage(0, 0); CP_COMMIT();
    load_stage(1, 1); CP_COMMIT();

    float d[2][8][4];
    #pragma unroll
    for (int i = 0; i < 2; i++)
        #pragma unroll
        for (int j = 0; j < 8; j++)
            #pragma unroll
            for (int r = 0; r < 4; r++) d[i][j][r] = 0.f;

    // ldmatrix lane addressing (same formula for A and B-trans)
    const int lrow = lane & 15;
    const int lcol = (lane >> 4) * 8;

    for (int c = 0; c < KT; c++) {
        CP_WAIT1();
        __syncthreads();
        const uint32_t st = sb + (c & 1) * STAGE_B;

        #pragma unroll
        for (int ks = 0; ks < 2; ks++) {
            uint32_t ah[2][4], al[2][4];
            #pragma unroll
            for (int mb = 0; mb < 2; mb++) {
                const uint32_t aoff = st + ((wm + mb * 16 + lrow) * LDA + ks * 16 + lcol) * 2;
                LDSM_X4(ah[mb][0], ah[mb][1], ah[mb][2], ah[mb][3], aoff + OFF_AH);
                LDSM_X4(al[mb][0], al[mb][1], al[mb][2], al[mb][3], aoff + OFF_AL);
            }
            uint32_t bh[4][4], bl[4][4];
            #pragma unroll
            for (int ng = 0; ng < 4; ng++) {
                const uint32_t boff = st + ((ks * 16 + lrow) * LDB + wn + ng * 16 + lcol) * 2;
                LDSM_X4T(bh[ng][0], bh[ng][1], bh[ng][2], bh[ng][3], boff + OFF_BH);
                LDSM_X4T(bl[ng][0], bl[ng][1], bl[ng][2], bl[ng][3], boff + OFF_BL);
            }
            #pragma unroll
            for (int mb = 0; mb < 2; mb++) {
                #pragma unroll
                for (int ng = 0; ng < 4; ng++) {
                    MMA_BF16(d[mb][ng * 2 + 0], ah[mb], bh[ng][0], bh[ng][1]);
                    MMA_BF16(d[mb][ng * 2 + 1], ah[mb], bh[ng][2], bh[ng][3]);
                    MMA_BF16(d[mb][ng * 2 + 0], ah[mb], bl[ng][0], bl[ng][1]);
                    MMA_BF16(d[mb][ng * 2 + 1], ah[mb], bl[ng][2], bl[ng][3]);
                    MMA_BF16(d[mb][ng * 2 + 0], al[mb], bh[ng][0], bh[ng][1]);
                    MMA_BF16(d[mb][ng * 2 + 1], al[mb], bh[ng][2], bh[ng][3]);
                }
            }
        }
        __syncthreads();
        if (c + 2 < KT) { load_stage(c & 1, c + 2); }
        CP_COMMIT();   // keep group count in lockstep even when empty
    }

    // epilogue: d-fragment -> C
    #pragma unroll
    for (int mb = 0; mb < 2; mb++) {
        const int row = m0 + wm + mb * 16 + (lane >> 2);
        #pragma unroll
        for (int nb8 = 0; nb8 < 8; nb8++) {
            const int col = n0 + wn + nb8 * 8 + (lane & 3) * 2;
            float2 v0 = make_float2(d[mb][nb8][0], d[mb][nb8][1]);
            float2 v1 = make_float2(d[mb][nb8][2], d[mb][nb8][3]);
            *reinterpret_cast<float2*>(C + (size_t)row * N + col) = v0;
            *reinterpret_cast<float2*>(C + (size_t)(row + 8) * N + col) = v1;
        }
    }
}

// ---------------------------------------------------------------------------
// RoPE (unchanged)
// ---------------------------------------------------------------------------
__global__ void rope_kernel(const float* __restrict__ fcos, const float* __restrict__ fsin)
{
    const int s = blockIdx.x;
    const float* crow = fcos + (size_t)s * (HD / 2);
    const float* srow = fsin + (size_t)s * (HD / 2);
    float* row = g_qkv + (size_t)s * QKV_N;
    for (int p = threadIdx.x; p < (NH + NKV) * (HD / 2); p += blockDim.x) {
        const int h = p / (HD / 2);
        const int d = p % (HD / 2);
        const float c  = crow[d];
        const float sn = srow[d];
        const float x1 = row[h * HD + d];
        const float x2 = row[h * HD + d + HD / 2];
        row[h * HD + d]          = x1 * c - x2 * sn;
        row[h * HD + d + HD / 2] = x1 * sn + x2 * c;
    }
}

// ---------------------------------------------------------------------------
// Flash attention with sliding window + softcap (unchanged from R1)
// ---------------------------------------------------------------------------
#define BQ   64
#define BKV  32
#define QPAD (HD + 4)

__global__ void __launch_bounds__(256, 1) attn_kernel()
{
    extern __shared__ float sm[];
    float* sQ   = sm;
    float* sK   = sQ + BQ * QPAD;
    float* sV   = sK + BKV * QPAD;
    float* sP   = sV + BKV * QPAD;
    float* sSum = sP + BQ * 33;

    const int tid = threadIdx.x;
    const int tx  = tid & 15;
    const int ty  = tid >> 4;
    const int q0  = blockIdx.x * BQ;
    const int h   = blockIdx.y;
    const int kvh = h >> 1;

    for (int i = tid; i < BQ * HD; i += 256) {
        const int r = i >> 8;
        const int d = i & 255;
        sQ[r * QPAD + d] = g_qkv[(size_t)(q0 + r) * QKV_N + h * HD + d] * SCALING;
    }
    if (tid < BQ) sSum[tid] = 0.f;

    float acc[4][16] = {};
    float psum[4]    = {0.f, 0.f, 0.f, 0.f};

    const int klo      = max(0, q0 - (WIN - 1));
    const int kb_start = (klo / BKV) * BKV;
    const int kb_end   = q0 + BQ;

    __syncthreads();

    for (int kb = kb_start; kb < kb_end; kb += BKV) {
        for (int i = tid; i < BKV * (HD / 4); i += 256) {
            const int r  = i / (HD / 4);
            const int d4 = i % (HD / 4);
            const size_t base = (size_t)(kb + r) * QKV_N;
            float4 k4 = *reinterpret_cast<const float4*>(&g_qkv[base + (NH + kvh) * HD + d4 * 4]);
            *reinterpret_cast<float4*>(&sK[r * QPAD + d4 * 4]) = k4;
            float4 v4 = *reinterpret_cast<const float4*>(&g_qkv[base + (NH + NKV + kvh) * HD + d4 * 4]);
            *reinterpret_cast<float4*>(&sV[r * QPAD + d4 * 4]) = v4;
        }
        __syncthreads();

        float sacc[4][2] = {};
        #pragma unroll 8
        for (int d4 = 0; d4 < HD / 4; d4++) {
            float4 qv[4];
            #pragma unroll
            for (int i = 0; i < 4; i++)
                qv[i] = *reinterpret_cast<const float4*>(&sQ[(ty * 4 + i) * QPAD + d4 * 4]);
            float4 kv[2];
            #pragma unroll
            for (int j = 0; j < 2; j++)
                kv[j] = *reinterpret_cast<const float4*>(&sK[(tx * 2 + j) * QPAD + d4 * 4]);
            #pragma unroll
            for (int i = 0; i < 4; i++)
                #pragma unroll
                for (int j = 0; j < 2; j++)
                    sacc[i][j] += qv[i].x * kv[j].x + qv[i].y * kv[j].y
                                + qv[i].z * kv[j].z + qv[i].w * kv[j].w;
        }

        #pragma unroll
        for (int i = 0; i < 4; i++) {
            const int q = q0 + ty * 4 + i;
            #pragma unroll
            for (int j = 0; j < 2; j++) {
                const int k = kb + tx * 2 + j;
                const float t = tanhf(sacc[i][j] * (1.0f / SOFTCAP)) * SOFTCAP;
                float p = __expf(t - SOFTCAP);
                const bool valid = (k <= q) && (q - k < WIN);
                p = valid ? p : 0.f;
                sP[(ty * 4 + i) * 33 + tx * 2 + j] = p;
                psum[i] += p;
            }
        }
        __syncthreads();

        #pragma unroll
        for (int kk = 0; kk < BKV; kk++) {
            float pv[4];
            #pragma unroll
            for (int i = 0; i < 4; i++) pv[i] = sP[(ty * 4 + i) * 33 + kk];
            float4 vv[4];
            #pragma unroll
            for (int j4 = 0; j4 < 4; j4++)
                vv[j4] = *reinterpret_cast<const float4*>(&sV[kk * QPAD + tx * 16 + j4 * 4]);
            #pragma unroll
            for (int i = 0; i < 4; i++) {
                #pragma unroll
                for (int j4 = 0; j4 < 4; j4++) {
                    acc[i][j4 * 4 + 0] += pv[i] * vv[j4].x;
                    acc[i][j4 * 4 + 1] += pv[i] * vv[j4].y;
                    acc[i][j4 * 4 + 2] += pv[i] * vv[j4].z;
                    acc[i][j4 * 4 + 3] += pv[i] * vv[j4].w;
                }
            }
        }
        __syncthreads();
    }

    #pragma unroll
    for (int i = 0; i < 4; i++) atomicAdd(&sSum[ty * 4 + i], psum[i]);
    __syncthreads();

    #pragma unroll
    for (int i = 0; i < 4; i++) {
        const size_t q  = q0 + ty * 4 + i;
        const float inv = 1.0f / sSum[ty * 4 + i];
        #pragma unroll
        for (int j4 = 0; j4 < 4; j4++) {
            float4 o;
            o.x = acc[i][j4 * 4 + 0] * inv;
            o.y = acc[i][j4 * 4 + 1] * inv;
            o.z = acc[i][j4 * 4 + 2] * inv;
            o.w = acc[i][j4 * 4 + 3] * inv;
            *reinterpret_cast<float4*>(&g_attn[q * ATTN_N + h * HD + tx * 16 + j4 * 4]) = o;
        }
    }
}

// ---------------------------------------------------------------------------
extern "C" void kernel_launch(void* const* d_in, const int* in_sizes, int n_in,
                              void* d_out, int out_size)
{
    const float* hidden = (const float*)d_in[0];
    const float* Wqkv   = (const float*)d_in[1];
    const float* Wo     = (const float*)d_in[2];
    const float* fcos   = (const float*)d_in[3];
    const float* fsin   = (const float*)d_in[4];
    float* out = (float*)d_out;

    float *qkv_ptr, *attn_ptr;
    __nv_bfloat16 *Ah, *Al, *Bh, *Bl;
    cudaGetSymbolAddress((void**)&qkv_ptr,  g_qkv);
    cudaGetSymbolAddress((void**)&attn_ptr, g_attn);
    cudaGetSymbolAddress((void**)&Ah, g_Ah);
    cudaGetSymbolAddress((void**)&Al, g_Al);
    cudaGetSymbolAddress((void**)&Bh, g_Bh);
    cudaGetSymbolAddress((void**)&Bl, g_Bl);

    const int gemm_smem = NSTG * STAGE_B;   // 75776
    const int attn_smem = (BQ * QPAD + 2 * BKV * QPAD + BQ * 33 + BQ) * (int)sizeof(float);
    cudaFuncSetAttribute(gemm_mma, cudaFuncAttributeMaxDynamicSharedMemorySize, gemm_smem);
    cudaFuncSetAttribute(attn_kernel, cudaFuncAttributeMaxDynamicSharedMemorySize, attn_smem);

    // --- QKV projection: [2048,3584] @ [3584,8192] -> g_qkv ---
    conv_split<<<(S_LEN * HID_DIM / 4) / 256, 256>>>(
        (const float4*)hidden, (__nv_bfloat162*)Ah, (__nv_bfloat162*)Al);
    conv_split<<<((size_t)HID_DIM * QKV_N / 4) / 256, 256>>>(
        (const float4*)Wqkv, (__nv_bfloat162*)Bh, (__nv_bfloat162*)Bl);
    gemm_mma<<<dim3(QKV_N / BN, S_LEN / BM), 256, gemm_smem>>>(Ah, Al, Bh, Bl,
                                                               qkv_ptr, QKV_N, HID_DIM);

    // --- RoPE ---
    rope_kernel<<<S_LEN, 256>>>(fcos, fsin);

    // --- Attention ---
    attn_kernel<<<dim3(S_LEN / BQ, NH), 256, attn_smem>>>();

    // --- Output projection: [2048,4096] @ [4096,3584] -> out ---
    conv_split<<<(S_LEN * ATTN_N / 4) / 256, 256>>>(
        (const float4*)attn_ptr, (__nv_bfloat162*)Ah, (__nv_bfloat162*)Al);
    conv_split<<<((size_t)ATTN_N * HID_DIM / 4) / 256, 256>>>(
        (const float4*)Wo, (__nv_bfloat162*)Bh, (__nv_bfloat162*)Bl);
    gemm_mma<<<dim3(HID_DIM / BN, S_LEN / BM), 256, gemm_smem>>>(Ah, Al, Bh, Bl,
                                                                 out, HID_DIM, ATTN_N);
}

// round 4
// speedup vs baseline: 3.2327x; 1.6015x over previous
#include <cuda_runtime.h>
#include <cuda_bf16.h>
#include <math.h>
#include <stdint.h>

#define S_LEN   2048
#define HID_DIM 3584
#define NH      16
#define NKV     8
#define HD      256
#define QKV_N   ((NH + 2 * NKV) * HD)   // 8192
#define ATTN_N  (NH * HD)               // 4096
#define WIN     1024
#define SOFTCAP 50.0f
#define SCALING 0.0625f

// ---------------- scratch (__device__ globals; no allocs allowed) ----------
__device__ __align__(256) float g_qkv[S_LEN * QKV_N];    // 64 MB
__device__ __align__(256) __nv_bfloat16 g_Ah[S_LEN * 4096];
__device__ __align__(256) __nv_bfloat16 g_Al[S_LEN * 4096];
__device__ __align__(256) __nv_bfloat16 g_Bh[8192 * 3584];
__device__ __align__(256) __nv_bfloat16 g_Bl[8192 * 3584];
// per-head bf16 planes for attention
__device__ __align__(256) __nv_bfloat16 g_Qh[NH  * S_LEN * HD];
__device__ __align__(256) __nv_bfloat16 g_Ql[NH  * S_LEN * HD];
__device__ __align__(256) __nv_bfloat16 g_Kh[NKV * S_LEN * HD];
__device__ __align__(256) __nv_bfloat16 g_Kl[NKV * S_LEN * HD];
__device__ __align__(256) __nv_bfloat16 g_Vh[NKV * S_LEN * HD];
__device__ __align__(256) __nv_bfloat16 g_Vl[NKV * S_LEN * HD];

// ---------------- PTX helpers ----------------------------------------------
__device__ __forceinline__ uint32_t smem_u32(const void* p) {
    uint32_t a;
    asm("{ .reg .u64 t; cvta.to.shared.u64 t, %1; cvt.u32.u64 %0, t; }" : "=r"(a) : "l"(p));
    return a;
}
#define CP_ASYNC16(dst, src) \
    asm volatile("cp.async.cg.shared.global [%0], [%1], 16;" :: "r"(dst), "l"(src) : "memory")
#define CP_COMMIT() asm volatile("cp.async.commit_group;" ::: "memory")
#define CP_WAIT1()  asm volatile("cp.async.wait_group 1;" ::: "memory")

#define LDSM_X4(r0, r1, r2, r3, addr) \
    asm volatile("ldmatrix.sync.aligned.m8n8.x4.shared.b16 {%0,%1,%2,%3}, [%4];" \
        : "=r"(r0), "=r"(r1), "=r"(r2), "=r"(r3) : "r"(addr))
#define LDSM_X4T(r0, r1, r2, r3, addr) \
    asm volatile("ldmatrix.sync.aligned.m8n8.x4.trans.shared.b16 {%0,%1,%2,%3}, [%4];" \
        : "=r"(r0), "=r"(r1), "=r"(r2), "=r"(r3) : "r"(addr))

#define MMA_BF16(d, a, b0, b1) \
    asm volatile("mma.sync.aligned.m16n8k16.row.col.f32.bf16.bf16.f32 " \
        "{%0,%1,%2,%3}, {%4,%5,%6,%7}, {%8,%9}, {%0,%1,%2,%3};" \
        : "+f"((d)[0]), "+f"((d)[1]), "+f"((d)[2]), "+f"((d)[3]) \
        : "r"((a)[0]), "r"((a)[1]), "r"((a)[2]), "r"((a)[3]), "r"(b0), "r"(b1))

__device__ __forceinline__ void split_bf16(float x, __nv_bfloat16& h, __nv_bfloat16& l) {
    h = __float2bfloat16_rn(x);
    l = __float2bfloat16_rn(x - __bfloat162float(h));
}
// split two floats into packed hi-pair / lo-pair
__device__ __forceinline__ void split2(float a, float b, uint32_t& hi, uint32_t& lo) {
    __nv_bfloat16 ha, la, hb, lb;
    split_bf16(a, ha, la); split_bf16(b, hb, lb);
    __nv_bfloat162 H; H.x = ha; H.y = hb;
    __nv_bfloat162 L; L.x = la; L.y = lb;
    hi = *reinterpret_cast<uint32_t*>(&H);
    lo = *reinterpret_cast<uint32_t*>(&L);
}

// ---------------------------------------------------------------------------
// conv_split: fp32 row-major -> hi/lo bf16, same layout. 4 elems/thread.
// ---------------------------------------------------------------------------
__global__ void conv_split(const float4* __restrict__ X, __nv_bfloat162* __restrict__ H,
                           __nv_bfloat162* __restrict__ L)
{
    const size_t i = (size_t)blockIdx.x * blockDim.x + threadIdx.x;
    float4 v = X[i];
    __nv_bfloat16 h0, l0, h1, l1, h2, l2, h3, l3;
    split_bf16(v.x, h0, l0); split_bf16(v.y, h1, l1);
    split_bf16(v.z, h2, l2); split_bf16(v.w, h3, l3);
    __nv_bfloat162 a, b, c, d;
    a.x = h0; a.y = h1;  b.x = h2; b.y = h3;
    c.x = l0; c.y = l1;  d.x = l2; d.y = l3;
    H[2 * i] = a; H[2 * i + 1] = b;
    L[2 * i] = c; L[2 * i + 1] = d;
}

// ---------------------------------------------------------------------------
// HMMA split-bf16 GEMM (unchanged from R3 — known good)
// ---------------------------------------------------------------------------
#define BM   128
#define BN   128
#define BK   32
#define LDA  40
#define LDB  136
#define TILE_A_B (128 * LDA * 2)
#define TILE_B_B (32 * LDB * 2)
#define OFF_AH   0
#define OFF_AL   (TILE_A_B)
#define OFF_BH   (2 * TILE_A_B)
#define OFF_BL   (2 * TILE_A_B + TILE_B_B)
#define STAGE_B  (2 * TILE_A_B + 2 * TILE_B_B)
#define NSTG 2

__global__ void __launch_bounds__(256, 1)
gemm_mma(const __nv_bfloat16* __restrict__ Ah, const __nv_bfloat16* __restrict__ Al,
         const __nv_bfloat16* __restrict__ Bh, const __nv_bfloat16* __restrict__ Bl,
         float* __restrict__ C, int N, int K)
{
    extern __shared__ char smbuf[];
    const uint32_t sb = smem_u32(smbuf);

    const int tid  = threadIdx.x;
    const int lane = tid & 31;
    const int wid  = tid >> 5;
    const int wm   = (wid & 3) * 32;
    const int wn   = (wid >> 2) * 64;
    const int nb   = blockIdx.x, mbk = blockIdx.y;
    const int m0   = mbk * BM, n0 = nb * BN;
    const int KT   = K / BK;

    const int ar = tid >> 1, ac = (tid & 1) * 16;
    const int br = tid >> 3, bc = (tid & 7) * 16;

    const __nv_bfloat16* gAh = Ah + (size_t)(m0 + ar) * K + ac;
    const __nv_bfloat16* gAl = Al + (size_t)(m0 + ar) * K + ac;
    const __nv_bfloat16* gBh = Bh + (size_t)br * N + n0 + bc;
    const __nv_bfloat16* gBl = Bl + (size_t)br * N + n0 + bc;

    auto load_stage = [&](int s, int c) {
        const uint32_t st = sb + s * STAGE_B;
        const size_t ka = (size_t)c * BK;
        const uint32_t sa = st + (ar * LDA + ac) * 2;
        CP_ASYNC16(sa + OFF_AH,      gAh + ka);
        CP_ASYNC16(sa + OFF_AH + 16, gAh + ka + 8);
        CP_ASYNC16(sa + OFF_AL,      gAl + ka);
        CP_ASYNC16(sa + OFF_AL + 16, gAl + ka + 8);
        const uint32_t sbm = st + (br * LDB + bc) * 2;
        const size_t kb = (size_t)c * BK * N;
        CP_ASYNC16(sbm + OFF_BH,      gBh + kb);
        CP_ASYNC16(sbm + OFF_BH + 16, gBh + kb + 8);
        CP_ASYNC16(sbm + OFF_BL,      gBl + kb);
        CP_ASYNC16(sbm + OFF_BL + 16, gBl + kb + 8);
    };

    load_stage(0, 0); CP_COMMIT();
    load_stage(1, 1); CP_COMMIT();

    float d[2][8][4];
    #pragma unroll
    for (int i = 0; i < 2; i++)
        #pragma unroll
        for (int j = 0; j < 8; j++)
            #pragma unroll
            for (int r = 0; r < 4; r++) d[i][j][r] = 0.f;

    const int lrow = lane & 15;
    const int lcol = (lane >> 4) * 8;

    for (int c = 0; c < KT; c++) {
        CP_WAIT1();
        __syncthreads();
        const uint32_t st = sb + (c & 1) * STAGE_B;

        #pragma unroll
        for (int ks = 0; ks < 2; ks++) {
            uint32_t ah[2][4], al[2][4];
            #pragma unroll
            for (int mb = 0; mb < 2; mb++) {
                const uint32_t aoff = st + ((wm + mb * 16 + lrow) * LDA + ks * 16 + lcol) * 2;
                LDSM_X4(ah[mb][0], ah[mb][1], ah[mb][2], ah[mb][3], aoff + OFF_AH);
                LDSM_X4(al[mb][0], al[mb][1], al[mb][2], al[mb][3], aoff + OFF_AL);
            }
            uint32_t bh[4][4], bl[4][4];
            #pragma unroll
            for (int ng = 0; ng < 4; ng++) {
                const uint32_t boff = st + ((ks * 16 + lrow) * LDB + wn + ng * 16 + lcol) * 2;
                LDSM_X4T(bh[ng][0], bh[ng][1], bh[ng][2], bh[ng][3], boff + OFF_BH);
                LDSM_X4T(bl[ng][0], bl[ng][1], bl[ng][2], bl[ng][3], boff + OFF_BL);
            }
            #pragma unroll
            for (int mb = 0; mb < 2; mb++) {
                #pragma unroll
                for (int ng = 0; ng < 4; ng++) {
                    MMA_BF16(d[mb][ng * 2 + 0], ah[mb], bh[ng][0], bh[ng][1]);
                    MMA_BF16(d[mb][ng * 2 + 1], ah[mb], bh[ng][2], bh[ng][3]);
                    MMA_BF16(d[mb][ng * 2 + 0], ah[mb], bl[ng][0], bl[ng][1]);
                    MMA_BF16(d[mb][ng * 2 + 1], ah[mb], bl[ng][2], bl[ng][3]);
                    MMA_BF16(d[mb][ng * 2 + 0], al[mb], bh[ng][0], bh[ng][1]);
                    MMA_BF16(d[mb][ng * 2 + 1], al[mb], bh[ng][2], bh[ng][3]);
                }
            }
        }
        __syncthreads();
        if (c + 2 < KT) { load_stage(c & 1, c + 2); }
        CP_COMMIT();
    }

    #pragma unroll
    for (int mb = 0; mb < 2; mb++) {
        const int row = m0 + wm + mb * 16 + (lane >> 2);
        #pragma unroll
        for (int nb8 = 0; nb8 < 8; nb8++) {
            const int col = n0 + wn + nb8 * 8 + (lane & 3) * 2;
            float2 v0 = make_float2(d[mb][nb8][0], d[mb][nb8][1]);
            float2 v1 = make_float2(d[mb][nb8][2], d[mb][nb8][3]);
            *reinterpret_cast<float2*>(C + (size_t)row * N + col) = v0;
            *reinterpret_cast<float2*>(C + (size_t)(row + 8) * N + col) = v1;
        }
    }
}

// ---------------------------------------------------------------------------
// rope_split: rope Q (scaled) and K, split Q/K/V into hi/lo bf16 head-planes.
// ---------------------------------------------------------------------------
__global__ void rope_split_kernel(const float* __restrict__ fcos, const float* __restrict__ fsin)
{
    const int s   = blockIdx.x;
    const int tid = threadIdx.x;
    const float* crow = fcos + (size_t)s * 128;
    const float* srow = fsin + (size_t)s * 128;
    const float* row  = g_qkv + (size_t)s * QKV_N;

    // Q: 16 heads x 128 pairs, scaled
    for (int p = tid; p < NH * 128; p += 256) {
        const int h = p >> 7, d = p & 127;
        const float c = crow[d], sn = srow[d];
        const float x1 = row[h * HD + d], x2 = row[h * HD + d + 128];
        const float y1 = (x1 * c - x2 * sn) * SCALING;
        const float y2 = (x1 * sn + x2 * c) * SCALING;
        const size_t o = ((size_t)h * S_LEN + s) * HD + d;
        __nv_bfloat16 hh, ll;
        split_bf16(y1, hh, ll); g_Qh[o] = hh; g_Ql[o] = ll;
        split_bf16(y2, hh, ll); g_Qh[o + 128] = hh; g_Ql[o + 128] = ll;
    }
    // K: 8 heads x 128 pairs
    for (int p = tid; p < NKV * 128; p += 256) {
        const int h = p >> 7, d = p & 127;
        const float c = crow[d], sn = srow[d];
        const float x1 = row[(NH + h) * HD + d], x2 = row[(NH + h) * HD + d + 128];
        const float y1 = x1 * c - x2 * sn;
        const float y2 = x1 * sn + x2 * c;
        const size_t o = ((size_t)h * S_LEN + s) * HD + d;
        __nv_bfloat16 hh, ll;
        split_bf16(y1, hh, ll); g_Kh[o] = hh; g_Kl[o] = ll;
        split_bf16(y2, hh, ll); g_Kh[o + 128] = hh; g_Kl[o + 128] = ll;
    }
    // V: 8 heads x 256
    for (int p = tid; p < NKV * HD; p += 256) {
        const int h = p >> 8, d = p & 255;
        const float v = row[(NH + NKV + h) * HD + d];
        const size_t o = ((size_t)h * S_LEN + s) * HD + d;
        __nv_bfloat16 hh, ll;
        split_bf16(v, hh, ll); g_Vh[o] = hh; g_Vl[o] = ll;
    }
}

// ---------------------------------------------------------------------------
// Tensor-core flash attention: split-bf16 for QK^T and PV (3 MMAs each).
// CTA = (64 queries, 1 head), 4 warps x 16 q-rows, BKV=32, double-buffered KV.
// Fixed softmax max (softcap bounds scores to +-50). Output -> g_Ah/g_Al split.
// ---------------------------------------------------------------------------
#define SROWB 528     // 264 bf16 per smem row: 16B row shift -> conflict-free ldmatrix
#define QPLANE (64 * SROWB)       // 33792 B
#define KVPLANE (32 * SROWB)      // 16896 B
#define KVSTAGE (4 * KVPLANE)     // 67584 B

__global__ void __launch_bounds__(128, 1) attn_mma_kernel()
{
    extern __shared__ char smv[];
    const uint32_t sb = smem_u32(smv);
    const uint32_t QH = sb, QL = sb + QPLANE, ST0 = sb + 2 * QPLANE;

    const int tid  = threadIdx.x;
    const int lane = tid & 31;
    const int wq   = tid >> 5;                 // warp -> 16 q rows
    const int q0   = blockIdx.x * 64;
    const int h    = blockIdx.y;
    const int kvh  = h >> 1;

    const int lrow  = lane & 15;
    const int lcolb = (lane >> 4) * 16;        // byte offset (8 bf16)
    const int g     = lane >> 2;
    const int t2    = (lane & 3) * 2;

    const __nv_bfloat16* pQh = g_Qh + ((size_t)h * S_LEN + q0) * HD;
    const __nv_bfloat16* pQl = g_Ql + ((size_t)h * S_LEN + q0) * HD;
    const __nv_bfloat16* bKh = g_Kh + (size_t)kvh * S_LEN * HD;
    const __nv_bfloat16* bKl = g_Kl + (size_t)kvh * S_LEN * HD;
    const __nv_bfloat16* bVh = g_Vh + (size_t)kvh * S_LEN * HD;
    const __nv_bfloat16* bVl = g_Vl + (size_t)kvh * S_LEN * HD;

    // Q tile load (once)
    for (int i = tid; i < 64 * 32; i += 128) {
        const int r = i >> 5, ch = i & 31;
        const uint32_t o = (uint32_t)r * SROWB + ch * 16;
        const size_t go = (size_t)r * HD + ch * 8;
        CP_ASYNC16(QH + o, pQh + go);
        CP_ASYNC16(QL + o, pQl + go);
    }

    auto load_kv = [&](int s, int kb) {
        const uint32_t base = ST0 + s * KVSTAGE;
        for (int i = tid; i < 32 * 32; i += 128) {
            const int r = i >> 5, ch = i & 31;
            const uint32_t o = (uint32_t)r * SROWB + ch * 16;
            const size_t go = (size_t)(kb + r) * HD + ch * 8;
            CP_ASYNC16(base + o,               bKh + go);
            CP_ASYNC16(base + KVPLANE + o,     bKl + go);
            CP_ASYNC16(base + 2 * KVPLANE + o, bVh + go);
            CP_ASYNC16(base + 3 * KVPLANE + o, bVl + go);
        }
    };

    const int klo = (q0 - (WIN - 1)) > 0 ? (q0 - (WIN - 1)) : 0;
    const int kb0 = klo & ~31;
    const int nch = (q0 + 64 - kb0) >> 5;

    load_kv(0, kb0); CP_COMMIT();
    if (nch > 1) load_kv(1, kb0 + 32);
    CP_COMMIT();

    float o[32][4];
    #pragma unroll
    for (int i = 0; i < 32; i++)
        #pragma unroll
        for (int r = 0; r < 4; r++) o[i][r] = 0.f;
    float rs0 = 0.f, rs1 = 0.f;
    const int qrow0 = q0 + wq * 16 + g;

    for (int ic = 0; ic < nch; ic++) {
        const int kb = kb0 + ic * 32;
        CP_WAIT1();
        __syncthreads();
        const uint32_t st = ST0 + (ic & 1) * KVSTAGE;

        // ---- S = Q K^T (3-way split) ----
        float sf[4][4];
        #pragma unroll
        for (int t = 0; t < 4; t++)
            #pragma unroll
            for (int r = 0; r < 4; r++) sf[t][r] = 0.f;

        #pragma unroll
        for (int dc = 0; dc < 16; dc++) {
            const uint32_t qa = QH + (uint32_t)(wq * 16 + lrow) * SROWB + dc * 32 + lcolb;
            uint32_t ah[4], al[4];
            LDSM_X4(ah[0], ah[1], ah[2], ah[3], qa);
            LDSM_X4(al[0], al[1], al[2], al[3], qa + QPLANE);
            #pragma unroll
            for (int kg = 0; kg < 2; kg++) {
                const uint32_t ka = st + (uint32_t)(kg * 16 + lrow) * SROWB + dc * 32 + lcolb;
                uint32_t bh[4], bl[4];
                LDSM_X4(bh[0], bh[1], bh[2], bh[3], ka);
                LDSM_X4(bl[0], bl[1], bl[2], bl[3], ka + KVPLANE);
                // tile kg*2   = kseq rows 0-7 of group: b = (m0, m2)
                // tile kg*2+1 = kseq rows 8-15:        b = (m1, m3)
                MMA_BF16(sf[kg * 2 + 0], ah, bh[0], bh[2]);
                MMA_BF16(sf[kg * 2 + 1], ah, bh[1], bh[3]);
                MMA_BF16(sf[kg * 2 + 0], ah, bl[0], bl[2]);
                MMA_BF16(sf[kg * 2 + 1], ah, bl[1], bl[3]);
                MMA_BF16(sf[kg * 2 + 0], al, bh[0], bh[2]);
                MMA_BF16(sf[kg * 2 + 1], al, bh[1], bh[3]);
            }
        }

        // ---- softcap + mask + exp(t-50), split-pack P ----
        uint32_t ph[4][2], pl[4][2];
        #pragma unroll
        for (int t = 0; t < 4; t++) {
            const int kcol = kb + t * 8 + t2;
            float pv[4];
            #pragma unroll
            for (int r = 0; r < 4; r++) {
                const int q = qrow0 + ((r >= 2) ? 8 : 0);
                const int k = kcol + (r & 1);
                const float tt = tanhf(sf[t][r] * (1.0f / SOFTCAP)) * SOFTCAP;
                float p = __expf(tt - SOFTCAP);
                pv[r] = (k <= q && (q - k) < WIN) ? p : 0.f;
            }
            rs0 += pv[0] + pv[1];
            rs1 += pv[2] + pv[3];
            split2(pv[0], pv[1], ph[t][0], pl[t][0]);
            split2(pv[2], pv[3], ph[t][1], pl[t][1]);
        }

        // ---- O += P V (3-way split) ----
        #pragma unroll
        for (int kg = 0; kg < 2; kg++) {
            uint32_t pah[4] = { ph[kg * 2][0], ph[kg * 2][1], ph[kg * 2 + 1][0], ph[kg * 2 + 1][1] };
            uint32_t pal[4] = { pl[kg * 2][0], pl[kg * 2][1], pl[kg * 2 + 1][0], pl[kg * 2 + 1][1] };
            #pragma unroll
            for (int dc = 0; dc < 16; dc++) {
                const uint32_t va = st + 2 * KVPLANE +
                    (uint32_t)(kg * 16 + lrow) * SROWB + dc * 32 + lcolb;
                uint32_t vh[4], vl[4];
                LDSM_X4T(vh[0], vh[1], vh[2], vh[3], va);
                LDSM_X4T(vl[0], vl[1], vl[2], vl[3], va + KVPLANE);
                MMA_BF16(o[dc * 2 + 0], pah, vh[0], vh[1]);
                MMA_BF16(o[dc * 2 + 1], pah, vh[2], vh[3]);
                MMA_BF16(o[dc * 2 + 0], pah, vl[0], vl[1]);
                MMA_BF16(o[dc * 2 + 1], pah, vl[2], vl[3]);
                MMA_BF16(o[dc * 2 + 0], pal, vh[0], vh[1]);
                MMA_BF16(o[dc * 2 + 1], pal, vh[2], vh[3]);
            }
        }
        __syncthreads();
        if (ic + 2 < nch) load_kv(ic & 1, kb + 64);
        CP_COMMIT();
    }

    // ---- row sums across the 4 lanes of each row group ----
    rs0 += __shfl_xor_sync(0xFFFFFFFFu, rs0, 1);
    rs0 += __shfl_xor_sync(0xFFFFFFFFu, rs0, 2);
    rs1 += __shfl_xor_sync(0xFFFFFFFFu, rs1, 1);
    rs1 += __shfl_xor_sync(0xFFFFFFFFu, rs1, 2);
    const float i0 = 1.0f / rs0, i1 = 1.0f / rs1;

    // ---- epilogue: normalize, split to hi/lo bf16, write to g_Ah/g_Al ----
    const int row0 = q0 + wq * 16 + g;
    #pragma unroll
    for (int t = 0; t < 32; t++) {
        const int col = h * HD + (t >> 1) * 16 + (t & 1) * 8 + t2;
        uint32_t hi, lo;
        split2(o[t][0] * i0, o[t][1] * i0, hi, lo);
        *reinterpret_cast<uint32_t*>(&g_Ah[(size_t)row0 * ATTN_N + col]) = hi;
        *reinterpret_cast<uint32_t*>(&g_Al[(size_t)row0 * ATTN_N + col]) = lo;
        split2(o[t][2] * i1, o[t][3] * i1, hi, lo);
        *reinterpret_cast<uint32_t*>(&g_Ah[(size_t)(row0 + 8) * ATTN_N + col]) = hi;
        *reinterpret_cast<uint32_t*>(&g_Al[(size_t)(row0 + 8) * ATTN_N + col]) = lo;
    }
}

// ---------------------------------------------------------------------------
extern "C" void kernel_launch(void* const* d_in, const int* in_sizes, int n_in,
                              void* d_out, int out_size)
{
    const float* hidden = (const float*)d_in[0];
    const float* Wqkv   = (const float*)d_in[1];
    const float* Wo     = (const float*)d_in[2];
    const float* fcos   = (const float*)d_in[3];
    const float* fsin   = (const float*)d_in[4];
    float* out = (float*)d_out;

    float* qkv_ptr;
    __nv_bfloat16 *Ah, *Al, *Bh, *Bl;
    cudaGetSymbolAddress((void**)&qkv_ptr, g_qkv);
    cudaGetSymbolAddress((void**)&Ah, g_Ah);
    cudaGetSymbolAddress((void**)&Al, g_Al);
    cudaGetSymbolAddress((void**)&Bh, g_Bh);
    cudaGetSymbolAddress((void**)&Bl, g_Bl);

    const int gemm_smem = NSTG * STAGE_B;                 // 75776
    const int attn_smem = 2 * QPLANE + 2 * KVSTAGE;       // 202752
    cudaFuncSetAttribute(gemm_mma, cudaFuncAttributeMaxDynamicSharedMemorySize, gemm_smem);
    cudaFuncSetAttribute(attn_mma_kernel, cudaFuncAttributeMaxDynamicSharedMemorySize, attn_smem);

    // --- QKV projection ---
    conv_split<<<(S_LEN * HID_DIM / 4) / 256, 256>>>(
        (const float4*)hidden, (__nv_bfloat162*)Ah, (__nv_bfloat162*)Al);
    conv_split<<<((size_t)HID_DIM * QKV_N / 4) / 256, 256>>>(
        (const float4*)Wqkv, (__nv_bfloat162*)Bh, (__nv_bfloat162*)Bl);
    gemm_mma<<<dim3(QKV_N / BN, S_LEN / BM), 256, gemm_smem>>>(Ah, Al, Bh, Bl,
                                                               qkv_ptr, QKV_N, HID_DIM);

    // --- RoPE + split into bf16 head planes ---
    rope_split_kernel<<<S_LEN, 256>>>(fcos, fsin);

    // --- Tensorized attention (writes g_Ah/g_Al directly) ---
    attn_mma_kernel<<<dim3(S_LEN / 64, NH), 128, attn_smem>>>();

    // --- Output projection ---
    conv_split<<<((size_t)ATTN_N * HID_DIM / 4) / 256, 256>>>(
        (const float4*)Wo, (__nv_bfloat162*)Bh, (__nv_bfloat162*)Bl);
    gemm_mma<<<dim3(HID_DIM / BN, S_LEN / BM), 256, gemm_smem>>>(Ah, Al, Bh, Bl,
                                                                 out, HID_DIM, ATTN_N);
}